// round 1
// baseline (speedup 1.0000x reference)
#include <cuda_runtime.h>
#include <math.h>

#define TT 2048
#define HH 2048
#define EE 8
#define II 4096
#define BM 64
#define BN 64
#define BK 16

// ---- scratch (device globals; no allocations allowed) ----
__device__ int   g_count[EE];
__device__ int   g_tok[EE * TT];
__device__ float g_wt[EE * TT];
__device__ float g_h[67108864];  // [EE][TT][II] fp32 = 256 MB

// ---------------------------------------------------------------------------
__global__ void zero_counts_k() {
    if (threadIdx.x < EE) g_count[threadIdx.x] = 0;
}

// One block per token. 8 warps = 8 expert logits. Softmax -> top2 -> renorm.
__global__ __launch_bounds__(256) void router_k(const float* __restrict__ x,
                                                const float* __restrict__ gw) {
    const int t = blockIdx.x;
    const int tid = threadIdx.x, w = tid >> 5, lane = tid & 31;
    __shared__ float logits[EE];
    const float* xr = x + (size_t)t * HH;
    const float* gr = gw + (size_t)w * HH;
    float s = 0.f;
    for (int k = lane; k < HH; k += 32) s = fmaf(xr[k], gr[k], s);
#pragma unroll
    for (int o = 16; o; o >>= 1) s += __shfl_xor_sync(0xffffffffu, s, o);
    if (lane == 0) logits[w] = s;
    __syncthreads();
    if (tid == 0) {
        float m = logits[0];
#pragma unroll
        for (int i = 1; i < EE; ++i) m = fmaxf(m, logits[i]);
        float p[EE];
#pragma unroll
        for (int i = 0; i < EE; ++i) p[i] = expf(logits[i] - m);
        // top-2 on probs; strict '>' keeps earliest index on ties (jax top_k order)
        int a = 0;
#pragma unroll
        for (int i = 1; i < EE; ++i) if (p[i] > p[a]) a = i;
        int b = (a == 0) ? 1 : 0;
#pragma unroll
        for (int i = 0; i < EE; ++i) if (i != a && p[i] > p[b]) b = i;
        const float r = 1.f / (p[a] + p[b]);
        int pa = atomicAdd(&g_count[a], 1);
        g_tok[a * TT + pa] = t; g_wt[a * TT + pa] = p[a] * r;
        int pb = atomicAdd(&g_count[b], 1);
        g_tok[b * TT + pb] = t; g_wt[b * TT + pb] = p[b] * r;
    }
}

// ---------------------------------------------------------------------------
// Grouped GEMM1 + fused SwiGLU + routing weight.
// A = gathered hidden rows [cnt x H], B = w13[e] gate rows [n] and up rows [I+n].
// h[e][slot][n] = wt * silu(g) * u
__global__ __launch_bounds__(256) void gemm1_swiglu(const float* __restrict__ x,
                                                    const float* __restrict__ w13) {
    const int e = blockIdx.z;
    const int cnt = g_count[e];
    const int m0 = blockIdx.y * BM;
    if (m0 >= cnt) return;
    const int n0 = blockIdx.x * BN;

    __shared__ float As[BK][BM + 4];
    __shared__ float Bg[BK][BN + 4];
    __shared__ float Bu[BK][BN + 4];

    const int tid = threadIdx.x;
    const int lm = tid >> 2;         // 0..63 tile row
    const int lk = (tid & 3) * 4;    // 0,4,8,12

    const int slot_l = m0 + lm;
    const bool a_valid = slot_l < cnt;
    const float* arow = x + (size_t)(a_valid ? g_tok[e * TT + slot_l] : 0) * HH;

    const float* bgrow = w13 + (size_t)e * 2 * II * HH + (size_t)(n0 + lm) * HH;
    const float* burow = bgrow + (size_t)II * HH;

    const int ty = tid >> 4;  // 0..15 -> m micro-row
    const int tx = tid & 15;  // 0..15 -> n micro-col

    float acc_g[4][4] = {};
    float acc_u[4][4] = {};

    for (int k0 = 0; k0 < HH; k0 += BK) {
        __syncthreads();
        float4 av = a_valid ? *(const float4*)(arow + k0 + lk)
                            : make_float4(0.f, 0.f, 0.f, 0.f);
        float4 gv = *(const float4*)(bgrow + k0 + lk);
        float4 uv = *(const float4*)(burow + k0 + lk);
        As[lk + 0][lm] = av.x; As[lk + 1][lm] = av.y;
        As[lk + 2][lm] = av.z; As[lk + 3][lm] = av.w;
        Bg[lk + 0][lm] = gv.x; Bg[lk + 1][lm] = gv.y;
        Bg[lk + 2][lm] = gv.z; Bg[lk + 3][lm] = gv.w;
        Bu[lk + 0][lm] = uv.x; Bu[lk + 1][lm] = uv.y;
        Bu[lk + 2][lm] = uv.z; Bu[lk + 3][lm] = uv.w;
        __syncthreads();
#pragma unroll
        for (int k = 0; k < BK; ++k) {
            float a[4], bg[4], bu[4];
#pragma unroll
            for (int i = 0; i < 4; ++i) a[i] = As[k][ty * 4 + i];
#pragma unroll
            for (int j = 0; j < 4; ++j) {
                bg[j] = Bg[k][tx * 4 + j];
                bu[j] = Bu[k][tx * 4 + j];
            }
#pragma unroll
            for (int i = 0; i < 4; ++i)
#pragma unroll
                for (int j = 0; j < 4; ++j) {
                    acc_g[i][j] = fmaf(a[i], bg[j], acc_g[i][j]);
                    acc_u[i][j] = fmaf(a[i], bu[j], acc_u[i][j]);
                }
        }
    }

#pragma unroll
    for (int i = 0; i < 4; ++i) {
        const int slot = m0 + ty * 4 + i;
        if (slot < cnt) {
            const float wt = g_wt[e * TT + slot];
            float* hrow = g_h + ((size_t)e * TT + slot) * II + n0 + tx * 4;
#pragma unroll
            for (int j = 0; j < 4; ++j) {
                const float g = acc_g[i][j];
                const float u = acc_u[i][j];
                const float sg = 1.f / (1.f + __expf(-g));
                hrow[j] = wt * (g * sg) * u;
            }
        }
    }
}

// ---------------------------------------------------------------------------
// Grouped GEMM2: out[tok] += h[e][slot] @ w2[e]^T  (atomic scatter-add)
__global__ __launch_bounds__(256) void gemm2_combine(const float* __restrict__ w2,
                                                     float* __restrict__ out) {
    const int e = blockIdx.z;
    const int cnt = g_count[e];
    const int m0 = blockIdx.y * BM;
    if (m0 >= cnt) return;
    const int n0 = blockIdx.x * BN;

    __shared__ float As[BK][BM + 4];
    __shared__ float Bs[BK][BN + 4];

    const int tid = threadIdx.x;
    const int lm = tid >> 2;
    const int lk = (tid & 3) * 4;

    const int slot_l = m0 + lm;
    const bool a_valid = slot_l < cnt;
    const float* arow = g_h + ((size_t)e * TT + (a_valid ? slot_l : 0)) * II;
    const float* brow = w2 + (size_t)e * HH * II + (size_t)(n0 + lm) * II;

    const int ty = tid >> 4, tx = tid & 15;
    float acc[4][4] = {};

    for (int k0 = 0; k0 < II; k0 += BK) {
        __syncthreads();
        float4 av = a_valid ? *(const float4*)(arow + k0 + lk)
                            : make_float4(0.f, 0.f, 0.f, 0.f);
        float4 bv = *(const float4*)(brow + k0 + lk);
        As[lk + 0][lm] = av.x; As[lk + 1][lm] = av.y;
        As[lk + 2][lm] = av.z; As[lk + 3][lm] = av.w;
        Bs[lk + 0][lm] = bv.x; Bs[lk + 1][lm] = bv.y;
        Bs[lk + 2][lm] = bv.z; Bs[lk + 3][lm] = bv.w;
        __syncthreads();
#pragma unroll
        for (int k = 0; k < BK; ++k) {
            float a[4], b[4];
#pragma unroll
            for (int i = 0; i < 4; ++i) a[i] = As[k][ty * 4 + i];
#pragma unroll
            for (int j = 0; j < 4; ++j) b[j] = Bs[k][tx * 4 + j];
#pragma unroll
            for (int i = 0; i < 4; ++i)
#pragma unroll
                for (int j = 0; j < 4; ++j)
                    acc[i][j] = fmaf(a[i], b[j], acc[i][j]);
        }
    }

#pragma unroll
    for (int i = 0; i < 4; ++i) {
        const int slot = m0 + ty * 4 + i;
        if (slot < cnt) {
            const int tok = g_tok[e * TT + slot];
            float* orow = out + (size_t)tok * HH + n0 + tx * 4;
#pragma unroll
            for (int j = 0; j < 4; ++j) atomicAdd(&orow[j], acc[i][j]);
        }
    }
}

// ---------------------------------------------------------------------------
extern "C" void kernel_launch(void* const* d_in, const int* in_sizes, int n_in,
                              void* d_out, int out_size) {
    const float* x   = (const float*)d_in[0];  // [T, H]
    const float* gw  = (const float*)d_in[1];  // [E, H]
    const float* w13 = (const float*)d_in[2];  // [E, 2I, H]
    const float* w2  = (const float*)d_in[3];  // [E, H, I]
    float* out = (float*)d_out;                // [T, H] fp32

    cudaMemsetAsync(out, 0, (size_t)TT * HH * sizeof(float));
    zero_counts_k<<<1, 32>>>();
    router_k<<<TT, 256>>>(x, gw);
    dim3 g1(II / BN, TT / BM, EE);
    gemm1_swiglu<<<g1, 256>>>(x, w13);
    dim3 g2(HH / BN, TT / BM, EE);
    gemm2_combine<<<g2, 256>>>(w2, out);
}

// round 2
// speedup vs baseline: 2.2286x; 2.2286x over previous
#include <cuda_runtime.h>
#include <math.h>
#include <stdint.h>

#define TT 2048
#define HH 2048
#define EE 8
#define II 4096

// ---- scratch (device globals; no allocations allowed) ----
__device__ int   g_count[EE];
__device__ int   g_tok[EE * TT];
__device__ float g_wt[EE * TT];
__device__ float g_h[67108864];  // [EE][TT][II] fp32 = 256 MB

// ---------------------------------------------------------------------------
__global__ void zero_counts_k() {
    if (threadIdx.x < EE) g_count[threadIdx.x] = 0;
}

// One block per token. 8 warps = 8 expert logits. Softmax -> top2 -> renorm.
// Exact fp32 (top-k selection must not flip under tf32 rounding).
__global__ __launch_bounds__(256) void router_k(const float* __restrict__ x,
                                                const float* __restrict__ gw) {
    const int t = blockIdx.x;
    const int tid = threadIdx.x, w = tid >> 5, lane = tid & 31;
    __shared__ float logits[EE];
    const float* xr = x + (size_t)t * HH;
    const float* gr = gw + (size_t)w * HH;
    float s = 0.f;
    for (int k = lane; k < HH; k += 32) s = fmaf(xr[k], gr[k], s);
#pragma unroll
    for (int o = 16; o; o >>= 1) s += __shfl_xor_sync(0xffffffffu, s, o);
    if (lane == 0) logits[w] = s;
    __syncthreads();
    if (tid == 0) {
        float m = logits[0];
#pragma unroll
        for (int i = 1; i < EE; ++i) m = fmaxf(m, logits[i]);
        float p[EE];
#pragma unroll
        for (int i = 0; i < EE; ++i) p[i] = expf(logits[i] - m);
        int a = 0;
#pragma unroll
        for (int i = 1; i < EE; ++i) if (p[i] > p[a]) a = i;
        int b = (a == 0) ? 1 : 0;
#pragma unroll
        for (int i = 0; i < EE; ++i) if (i != a && p[i] > p[b]) b = i;
        const float r = 1.f / (p[a] + p[b]);
        int pa = atomicAdd(&g_count[a], 1);
        g_tok[a * TT + pa] = t; g_wt[a * TT + pa] = p[a] * r;
        int pb = atomicAdd(&g_count[b], 1);
        g_tok[b * TT + pb] = t; g_wt[b * TT + pb] = p[b] * r;
    }
}

// ---------------------------------------------------------------------------
// tf32 helpers
__device__ __forceinline__ uint32_t f2tf(float f) {
    uint32_t r;
    asm volatile("cvt.rna.tf32.f32 %0, %1;" : "=r"(r) : "f"(f));
    return r;
}

__device__ __forceinline__ void mma8(float* c, const uint32_t* a,
                                     uint32_t b0, uint32_t b1) {
    asm volatile(
        "mma.sync.aligned.m16n8k8.row.col.f32.tf32.tf32.f32 "
        "{%0,%1,%2,%3},{%4,%5,%6,%7},{%8,%9},{%0,%1,%2,%3};"
        : "+f"(c[0]), "+f"(c[1]), "+f"(c[2]), "+f"(c[3])
        : "r"(a[0]), "r"(a[1]), "r"(a[2]), "r"(a[3]), "r"(b0), "r"(b1));
}

// smem row stride 36 words: bank = (4*row + col) % 32 -> conflict-free for
// the 8-row x 4-col fragment access patterns of m16n8k8.
#define SSTR 36

// ---------------------------------------------------------------------------
// GEMM1: h[e][slot][0:I] = wt * silu(x@Wg^T) * (x@Wu^T), tf32 tensor cores.
// BM=128, BN=64 (of each of gate/up), BK=32. 8 warps: 4 in M x 2 in N,
// warp tile 32x32 (2 m16 x 4 n8), dual accumulators (gate+up).
__global__ __launch_bounds__(256) void gemm1_tf32(const float* __restrict__ x,
                                                  const float* __restrict__ w13) {
    extern __shared__ uint32_t sm[];   // stage: A[128*36] Bg[64*36] Bu[64*36]
    const int STG = 128 * SSTR + 2 * 64 * SSTR;  // 9216 words

    const int e = blockIdx.z;
    const int cnt = g_count[e];
    const int m0 = blockIdx.y * 128;
    if (m0 >= cnt) return;
    const int n0 = blockIdx.x * 64;

    const int tid = threadIdx.x;
    // global->smem staging map
    const int ar = tid >> 1, ac = (tid & 1) * 16;          // A: 128 rows x 32
    const int br = tid >> 2, bc = (tid & 3) * 8;           // B: 64 rows x 32
    const int slotA = m0 + ar;
    const float* arow = x + (size_t)g_tok[e * TT + (slotA < cnt ? slotA : 0)] * HH + ac;
    const float* bgrow = w13 + (size_t)e * 2 * II * HH + (size_t)(n0 + br) * HH + bc;
    const float* burow = bgrow + (size_t)II * HH;

    const int lane = tid & 31, wid = tid >> 5;
    const int grp = lane >> 2, tig = lane & 3;
    const int wm = (wid & 3) * 32, wn = (wid >> 2) * 32;

    float cg[2][4][4] = {};
    float cu[2][4][4] = {};
    float4 pA[4], pG[2], pU[2];

    // prologue: fetch k0=0
#pragma unroll
    for (int j = 0; j < 4; ++j) pA[j] = *(const float4*)(arow + 4 * j);
#pragma unroll
    for (int j = 0; j < 2; ++j) {
        pG[j] = *(const float4*)(bgrow + 4 * j);
        pU[j] = *(const float4*)(burow + 4 * j);
    }

#define STS_STAGE(b)                                                          \
    {                                                                         \
        uint32_t* s = sm + (b) * STG;                                         \
        _Pragma("unroll") for (int j = 0; j < 4; ++j) {                       \
            uint4 v = {f2tf(pA[j].x), f2tf(pA[j].y), f2tf(pA[j].z), f2tf(pA[j].w)}; \
            *(uint4*)&s[ar * SSTR + ac + 4 * j] = v;                          \
        }                                                                     \
        _Pragma("unroll") for (int j = 0; j < 2; ++j) {                       \
            uint4 g = {f2tf(pG[j].x), f2tf(pG[j].y), f2tf(pG[j].z), f2tf(pG[j].w)}; \
            uint4 u = {f2tf(pU[j].x), f2tf(pU[j].y), f2tf(pU[j].z), f2tf(pU[j].w)}; \
            *(uint4*)&s[128 * SSTR + br * SSTR + bc + 4 * j] = g;             \
            *(uint4*)&s[128 * SSTR + 64 * SSTR + br * SSTR + bc + 4 * j] = u; \
        }                                                                     \
    }

    STS_STAGE(0);
    __syncthreads();

    int buf = 0;
    for (int k0 = 0; k0 < HH; k0 += 32) {
        const int nk = k0 + 32;
        if (nk < HH) {
#pragma unroll
            for (int j = 0; j < 4; ++j) pA[j] = *(const float4*)(arow + nk + 4 * j);
#pragma unroll
            for (int j = 0; j < 2; ++j) {
                pG[j] = *(const float4*)(bgrow + nk + 4 * j);
                pU[j] = *(const float4*)(burow + nk + 4 * j);
            }
        }
        {
            const uint32_t* sA = sm + buf * STG;
            const uint32_t* sG = sA + 128 * SSTR;
            const uint32_t* sU = sG + 64 * SSTR;
#pragma unroll
            for (int kc = 0; kc < 32; kc += 8) {
                uint32_t af[2][4];
#pragma unroll
                for (int i = 0; i < 2; ++i) {
                    const int r0 = wm + 16 * i + grp;
                    af[i][0] = sA[r0 * SSTR + kc + tig];
                    af[i][1] = sA[(r0 + 8) * SSTR + kc + tig];
                    af[i][2] = sA[r0 * SSTR + kc + tig + 4];
                    af[i][3] = sA[(r0 + 8) * SSTR + kc + tig + 4];
                }
#pragma unroll
                for (int j = 0; j < 4; ++j) {
                    const int rn = wn + 8 * j + grp;
                    const uint32_t bg0 = sG[rn * SSTR + kc + tig];
                    const uint32_t bg1 = sG[rn * SSTR + kc + tig + 4];
                    const uint32_t bu0 = sU[rn * SSTR + kc + tig];
                    const uint32_t bu1 = sU[rn * SSTR + kc + tig + 4];
#pragma unroll
                    for (int i = 0; i < 2; ++i) {
                        mma8(cg[i][j], af[i], bg0, bg1);
                        mma8(cu[i][j], af[i], bu0, bu1);
                    }
                }
            }
        }
        if (nk < HH) STS_STAGE(buf ^ 1);
        __syncthreads();
        buf ^= 1;
    }

    // epilogue: swiglu + routing weight -> g_h
#pragma unroll
    for (int i = 0; i < 2; ++i) {
#pragma unroll
        for (int half = 0; half < 2; ++half) {
            const int slot = m0 + wm + 16 * i + grp + 8 * half;
            if (slot < cnt) {
                const float wt = g_wt[e * TT + slot];
                float* hrow = g_h + ((size_t)e * TT + slot) * II + n0 + wn;
#pragma unroll
                for (int j = 0; j < 4; ++j) {
                    const float g0 = cg[i][j][2 * half], g1 = cg[i][j][2 * half + 1];
                    const float u0 = cu[i][j][2 * half], u1 = cu[i][j][2 * half + 1];
                    float2 v;
                    v.x = wt * (g0 / (1.f + __expf(-g0))) * u0;
                    v.y = wt * (g1 / (1.f + __expf(-g1))) * u1;
                    *(float2*)&hrow[8 * j + 2 * tig] = v;
                }
            }
        }
    }
#undef STS_STAGE
}

// ---------------------------------------------------------------------------
// GEMM2: out[tok] += h[e][slot] @ w2[e]^T (tf32, atomic scatter-add)
__global__ __launch_bounds__(256) void gemm2_tf32(const float* __restrict__ w2,
                                                  float* __restrict__ out) {
    extern __shared__ uint32_t sm[];   // stage: A[128*36] B[64*36]
    const int STG = 128 * SSTR + 64 * SSTR;  // 6912 words

    const int e = blockIdx.z;
    const int cnt = g_count[e];
    const int m0 = blockIdx.y * 128;
    if (m0 >= cnt) return;
    const int n0 = blockIdx.x * 64;

    const int tid = threadIdx.x;
    const int ar = tid >> 1, ac = (tid & 1) * 16;
    const int br = tid >> 2, bc = (tid & 3) * 8;
    const int slotA = m0 + ar;
    const float* arow = g_h + ((size_t)e * TT + (slotA < cnt ? slotA : 0)) * II + ac;
    const float* brow = w2 + (size_t)e * HH * II + (size_t)(n0 + br) * II + bc;

    const int lane = tid & 31, wid = tid >> 5;
    const int grp = lane >> 2, tig = lane & 3;
    const int wm = (wid & 3) * 32, wn = (wid >> 2) * 32;

    float cc[2][4][4] = {};
    float4 pA[4], pB[2];

#pragma unroll
    for (int j = 0; j < 4; ++j) pA[j] = *(const float4*)(arow + 4 * j);
#pragma unroll
    for (int j = 0; j < 2; ++j) pB[j] = *(const float4*)(brow + 4 * j);

#define STS_STAGE2(b)                                                         \
    {                                                                         \
        uint32_t* s = sm + (b) * STG;                                         \
        _Pragma("unroll") for (int j = 0; j < 4; ++j) {                       \
            uint4 v = {f2tf(pA[j].x), f2tf(pA[j].y), f2tf(pA[j].z), f2tf(pA[j].w)}; \
            *(uint4*)&s[ar * SSTR + ac + 4 * j] = v;                          \
        }                                                                     \
        _Pragma("unroll") for (int j = 0; j < 2; ++j) {                       \
            uint4 v = {f2tf(pB[j].x), f2tf(pB[j].y), f2tf(pB[j].z), f2tf(pB[j].w)}; \
            *(uint4*)&s[128 * SSTR + br * SSTR + bc + 4 * j] = v;             \
        }                                                                     \
    }

    STS_STAGE2(0);
    __syncthreads();

    int buf = 0;
    for (int k0 = 0; k0 < II; k0 += 32) {
        const int nk = k0 + 32;
        if (nk < II) {
#pragma unroll
            for (int j = 0; j < 4; ++j) pA[j] = *(const float4*)(arow + nk + 4 * j);
#pragma unroll
            for (int j = 0; j < 2; ++j) pB[j] = *(const float4*)(brow + nk + 4 * j);
        }
        {
            const uint32_t* sA = sm + buf * STG;
            const uint32_t* sB = sA + 128 * SSTR;
#pragma unroll
            for (int kc = 0; kc < 32; kc += 8) {
                uint32_t af[2][4];
#pragma unroll
                for (int i = 0; i < 2; ++i) {
                    const int r0 = wm + 16 * i + grp;
                    af[i][0] = sA[r0 * SSTR + kc + tig];
                    af[i][1] = sA[(r0 + 8) * SSTR + kc + tig];
                    af[i][2] = sA[r0 * SSTR + kc + tig + 4];
                    af[i][3] = sA[(r0 + 8) * SSTR + kc + tig + 4];
                }
#pragma unroll
                for (int j = 0; j < 4; ++j) {
                    const int rn = wn + 8 * j + grp;
                    const uint32_t b0 = sB[rn * SSTR + kc + tig];
                    const uint32_t b1 = sB[rn * SSTR + kc + tig + 4];
#pragma unroll
                    for (int i = 0; i < 2; ++i) mma8(cc[i][j], af[i], b0, b1);
                }
            }
        }
        if (nk < II) STS_STAGE2(buf ^ 1);
        __syncthreads();
        buf ^= 1;
    }

#pragma unroll
    for (int i = 0; i < 2; ++i) {
#pragma unroll
        for (int half = 0; half < 2; ++half) {
            const int slot = m0 + wm + 16 * i + grp + 8 * half;
            if (slot < cnt) {
                const int tok = g_tok[e * TT + slot];
                float* orow = out + (size_t)tok * HH + n0 + wn;
#pragma unroll
                for (int j = 0; j < 4; ++j) {
                    atomicAdd(&orow[8 * j + 2 * tig], cc[i][j][2 * half]);
                    atomicAdd(&orow[8 * j + 2 * tig + 1], cc[i][j][2 * half + 1]);
                }
            }
        }
    }
#undef STS_STAGE2
}

// ---------------------------------------------------------------------------
extern "C" void kernel_launch(void* const* d_in, const int* in_sizes, int n_in,
                              void* d_out, int out_size) {
    const float* x   = (const float*)d_in[0];  // [T, H]
    const float* gw  = (const float*)d_in[1];  // [E, H]
    const float* w13 = (const float*)d_in[2];  // [E, 2I, H]
    const float* w2  = (const float*)d_in[3];  // [E, H, I]
    float* out = (float*)d_out;                // [T, H] fp32

    const int smem1 = (128 * SSTR + 2 * 64 * SSTR) * 2 * 4;  // 73728 B
    const int smem2 = (128 * SSTR + 64 * SSTR) * 2 * 4;      // 55296 B
    cudaFuncSetAttribute(gemm1_tf32, cudaFuncAttributeMaxDynamicSharedMemorySize, smem1);
    cudaFuncSetAttribute(gemm2_tf32, cudaFuncAttributeMaxDynamicSharedMemorySize, smem2);

    cudaMemsetAsync(out, 0, (size_t)TT * HH * sizeof(float));
    zero_counts_k<<<1, 32>>>();
    router_k<<<TT, 256>>>(x, gw);
    dim3 g1(II / 64, TT / 128, EE);
    gemm1_tf32<<<g1, 256, smem1>>>(x, w13);
    dim3 g2(HH / 64, TT / 128, EE);
    gemm2_tf32<<<g2, 256, smem2>>>(w2, out);
}

// round 4
// speedup vs baseline: 3.1116x; 1.3962x over previous
#include <cuda_runtime.h>
#include <math.h>
#include <stdint.h>

#define TT 2048
#define HH 2048
#define EE 8
#define II 4096
#define SROW 20           // padded smem row stride (words) -> conflict-free frags
#define STG_W 5120        // words per pipeline stage (A 2560 + B 2560)
#define NSTAGE 4

// ---- scratch (device globals; no allocations allowed) ----
__device__ int   g_count[EE];
__device__ int   g_tok[EE * TT];
__device__ float g_wt[EE * TT];
__device__ float g_h[67108864];  // [EE][TT][II] fp32 = 256 MB

// ---------------------------------------------------------------------------
__global__ void zero_counts_k() {
    if (threadIdx.x < EE) g_count[threadIdx.x] = 0;
}

// One block per token. 8 warps = 8 expert logits. Exact fp32 routing.
__global__ __launch_bounds__(256) void router_k(const float* __restrict__ x,
                                                const float* __restrict__ gw) {
    const int t = blockIdx.x;
    const int tid = threadIdx.x, w = tid >> 5, lane = tid & 31;
    __shared__ float logits[EE];
    const float* xr = x + (size_t)t * HH;
    const float* gr = gw + (size_t)w * HH;
    float s = 0.f;
    for (int k = lane; k < HH; k += 32) s = fmaf(xr[k], gr[k], s);
#pragma unroll
    for (int o = 16; o; o >>= 1) s += __shfl_xor_sync(0xffffffffu, s, o);
    if (lane == 0) logits[w] = s;
    __syncthreads();
    if (tid == 0) {
        float m = logits[0];
#pragma unroll
        for (int i = 1; i < EE; ++i) m = fmaxf(m, logits[i]);
        float p[EE];
#pragma unroll
        for (int i = 0; i < EE; ++i) p[i] = expf(logits[i] - m);
        int a = 0;
#pragma unroll
        for (int i = 1; i < EE; ++i) if (p[i] > p[a]) a = i;
        int b = (a == 0) ? 1 : 0;
#pragma unroll
        for (int i = 0; i < EE; ++i) if (i != a && p[i] > p[b]) b = i;
        const float r = 1.f / (p[a] + p[b]);
        int pa = atomicAdd(&g_count[a], 1);
        g_tok[a * TT + pa] = t; g_wt[a * TT + pa] = p[a] * r;
        int pb = atomicAdd(&g_count[b], 1);
        g_tok[b * TT + pb] = t; g_wt[b * TT + pb] = p[b] * r;
    }
}

// ---------------------------------------------------------------------------
__device__ __forceinline__ uint32_t f2tf(float f) {
    uint32_t r;
    asm("cvt.rna.tf32.f32 %0, %1;" : "=r"(r) : "f"(f));
    return r;
}
__device__ __forceinline__ void mma8(float* c, const uint32_t* a,
                                     uint32_t b0, uint32_t b1) {
    asm volatile(
        "mma.sync.aligned.m16n8k8.row.col.f32.tf32.tf32.f32 "
        "{%0,%1,%2,%3},{%4,%5,%6,%7},{%8,%9},{%0,%1,%2,%3};"
        : "+f"(c[0]), "+f"(c[1]), "+f"(c[2]), "+f"(c[3])
        : "r"(a[0]), "r"(a[1]), "r"(a[2]), "r"(a[3]), "r"(b0), "r"(b1));
}
#define CP16(so, gp) \
    asm volatile("cp.async.cg.shared.global [%0], [%1], 16;" :: "r"(so), "l"(gp))
#define CP_COMMIT() asm volatile("cp.async.commit_group;" ::: "memory")
#define CP_WAIT2()  asm volatile("cp.async.wait_group 2;" ::: "memory")
#define CP_WAIT0()  asm volatile("cp.async.wait_group 0;" ::: "memory")

// ---------------------------------------------------------------------------
// GEMM1: block 128(M) x 64(N of gate AND up), BK=16, 4-stage cp.async.
// Warps 4(M) x 2(N); warp tile 32x32 dual-accumulator (gate+up).
__global__ __launch_bounds__(256, 2) void gemm1_tf32(const float* __restrict__ x,
                                                     const float* __restrict__ w13) {
    extern __shared__ float sm[];
    const int e = blockIdx.z;
    const int cnt = g_count[e];
    const int m0 = blockIdx.y * 128;
    if (m0 >= cnt) return;
    const int n0 = blockIdx.x * 64;

    const int tid = threadIdx.x;
    const uint32_t sbase = (uint32_t)__cvta_generic_to_shared(sm);

    // loader: 4 cells/thread/stage (2 A rows, 1 gate row, 1 up row)
    const int r0 = tid >> 2, cg = tid & 3;
    int sl0 = m0 + r0;       if (sl0 > cnt - 1) sl0 = cnt - 1;
    int sl1 = m0 + 64 + r0;  if (sl1 > cnt - 1) sl1 = cnt - 1;
    const float* aG0 = x + (size_t)g_tok[e * TT + sl0] * HH + cg * 4;
    const float* aG1 = x + (size_t)g_tok[e * TT + sl1] * HH + cg * 4;
    const float* bG0 = w13 + (size_t)e * 2 * II * HH + (size_t)(n0 + r0) * HH + cg * 4;
    const float* bG1 = bG0 + (size_t)II * HH;
    const uint32_t aS0 = (r0 * SROW + cg * 4) * 4;
    const uint32_t aS1 = ((64 + r0) * SROW + cg * 4) * 4;
    const uint32_t bS0 = ((128 + r0) * SROW + cg * 4) * 4;
    const uint32_t bS1 = ((192 + r0) * SROW + cg * 4) * 4;

#define ISSUE1(s, k0)                                      \
    {                                                      \
        const uint32_t sb = sbase + (s) * (STG_W * 4);     \
        CP16(sb + aS0, aG0 + (k0));                        \
        CP16(sb + aS1, aG1 + (k0));                        \
        CP16(sb + bS0, bG0 + (k0));                        \
        CP16(sb + bS1, bG1 + (k0));                        \
    }

    const int lane = tid & 31, wid = tid >> 5;
    const int grp = lane >> 2, tig = lane & 3;
    const int wm = (wid & 3) * 32, wn = (wid >> 2) * 32;

    float cgr[2][4][4] = {};
    float cur[2][4][4] = {};

    ISSUE1(0, 0); CP_COMMIT();
    ISSUE1(1, 16); CP_COMMIT();
    ISSUE1(2, 32); CP_COMMIT();

    const int NT = HH / 16;  // 128
    for (int k = 0; k < NT; ++k) {
        CP_WAIT2();
        __syncthreads();
        const float* st = sm + (k & 3) * STG_W;
#pragma unroll
        for (int kc = 0; kc < 16; kc += 8) {
            uint32_t af[2][4];
#pragma unroll
            for (int i = 0; i < 2; ++i) {
                const float* pa = st + (wm + 16 * i + grp) * SROW + kc + tig;
                af[i][0] = f2tf(pa[0]);
                af[i][1] = f2tf(pa[8 * SROW]);
                af[i][2] = f2tf(pa[4]);
                af[i][3] = f2tf(pa[8 * SROW + 4]);
            }
#pragma unroll
            for (int j = 0; j < 4; ++j) {
                const float* pg = st + 128 * SROW + (wn + 8 * j + grp) * SROW + kc + tig;
                const uint32_t bg0 = f2tf(pg[0]);
                const uint32_t bg1 = f2tf(pg[4]);
                const uint32_t bu0 = f2tf(pg[64 * SROW]);
                const uint32_t bu1 = f2tf(pg[64 * SROW + 4]);
#pragma unroll
                for (int i = 0; i < 2; ++i) {
                    mma8(cgr[i][j], af[i], bg0, bg1);
                    mma8(cur[i][j], af[i], bu0, bu1);
                }
            }
        }
        const int kn = k + 3;
        if (kn < NT) ISSUE1(kn & 3, kn * 16);
        CP_COMMIT();
    }
    CP_WAIT0();

    // epilogue: swiglu * wt -> g_h
#pragma unroll
    for (int i = 0; i < 2; ++i) {
#pragma unroll
        for (int half = 0; half < 2; ++half) {
            const int slot = m0 + wm + 16 * i + grp + 8 * half;
            if (slot < cnt) {
                const float wt = g_wt[e * TT + slot];
                float* hrow = g_h + ((size_t)e * TT + slot) * II + n0 + wn;
#pragma unroll
                for (int j = 0; j < 4; ++j) {
                    const float g0 = cgr[i][j][2 * half], g1 = cgr[i][j][2 * half + 1];
                    const float u0 = cur[i][j][2 * half], u1 = cur[i][j][2 * half + 1];
                    float2 v;
                    v.x = wt * (g0 / (1.f + __expf(-g0))) * u0;
                    v.y = wt * (g1 / (1.f + __expf(-g1))) * u1;
                    *(float2*)&hrow[8 * j + 2 * tig] = v;
                }
            }
        }
    }
#undef ISSUE1
}

// ---------------------------------------------------------------------------
// GEMM2: block 128(M) x 128(N), BK=16, 4-stage cp.async.
// Warps 4(M) x 2(N); warp tile 32x64. Scatter atomicAdd epilogue.
__global__ __launch_bounds__(256, 2) void gemm2_tf32(const float* __restrict__ w2,
                                                     float* __restrict__ out) {
    extern __shared__ float sm[];
    const int e = blockIdx.z;
    const int cnt = g_count[e];
    const int m0 = blockIdx.y * 128;
    if (m0 >= cnt) return;
    const int n0 = blockIdx.x * 128;

    const int tid = threadIdx.x;
    const uint32_t sbase = (uint32_t)__cvta_generic_to_shared(sm);

    const int r0 = tid >> 2, cg = tid & 3;
    int sl0 = m0 + r0;       if (sl0 > cnt - 1) sl0 = cnt - 1;
    int sl1 = m0 + 64 + r0;  if (sl1 > cnt - 1) sl1 = cnt - 1;
    const float* aG0 = g_h + ((size_t)e * TT + sl0) * II + cg * 4;
    const float* aG1 = g_h + ((size_t)e * TT + sl1) * II + cg * 4;
    const float* bG0 = w2 + (size_t)e * HH * II + (size_t)(n0 + r0) * II + cg * 4;
    const float* bG1 = bG0 + (size_t)64 * II;
    const uint32_t aS0 = (r0 * SROW + cg * 4) * 4;
    const uint32_t aS1 = ((64 + r0) * SROW + cg * 4) * 4;
    const uint32_t bS0 = ((128 + r0) * SROW + cg * 4) * 4;
    const uint32_t bS1 = ((192 + r0) * SROW + cg * 4) * 4;

#define ISSUE2(s, k0)                                      \
    {                                                      \
        const uint32_t sb = sbase + (s) * (STG_W * 4);     \
        CP16(sb + aS0, aG0 + (k0));                        \
        CP16(sb + aS1, aG1 + (k0));                        \
        CP16(sb + bS0, bG0 + (k0));                        \
        CP16(sb + bS1, bG1 + (k0));                        \
    }

    const int lane = tid & 31, wid = tid >> 5;
    const int grp = lane >> 2, tig = lane & 3;
    const int wm = (wid & 3) * 32, wn = (wid >> 2) * 64;

    float cc[2][8][4] = {};

    ISSUE2(0, 0); CP_COMMIT();
    ISSUE2(1, 16); CP_COMMIT();
    ISSUE2(2, 32); CP_COMMIT();

    const int NT = II / 16;  // 256
    for (int k = 0; k < NT; ++k) {
        CP_WAIT2();
        __syncthreads();
        const float* st = sm + (k & 3) * STG_W;
#pragma unroll
        for (int kc = 0; kc < 16; kc += 8) {
            uint32_t af[2][4];
#pragma unroll
            for (int i = 0; i < 2; ++i) {
                const float* pa = st + (wm + 16 * i + grp) * SROW + kc + tig;
                af[i][0] = f2tf(pa[0]);
                af[i][1] = f2tf(pa[8 * SROW]);
                af[i][2] = f2tf(pa[4]);
                af[i][3] = f2tf(pa[8 * SROW + 4]);
            }
#pragma unroll
            for (int j = 0; j < 8; ++j) {
                const float* pb = st + 128 * SROW + (wn + 8 * j + grp) * SROW + kc + tig;
                const uint32_t b0 = f2tf(pb[0]);
                const uint32_t b1 = f2tf(pb[4]);
#pragma unroll
                for (int i = 0; i < 2; ++i) mma8(cc[i][j], af[i], b0, b1);
            }
        }
        const int kn = k + 3;
        if (kn < NT) ISSUE2(kn & 3, kn * 16);
        CP_COMMIT();
    }
    CP_WAIT0();

#pragma unroll
    for (int i = 0; i < 2; ++i) {
#pragma unroll
        for (int half = 0; half < 2; ++half) {
            const int slot = m0 + wm + 16 * i + grp + 8 * half;
            if (slot < cnt) {
                const int tok = g_tok[e * TT + slot];
                float* orow = out + (size_t)tok * HH + n0 + wn;
#pragma unroll
                for (int j = 0; j < 8; ++j) {
                    atomicAdd(&orow[8 * j + 2 * tig], cc[i][j][2 * half]);
                    atomicAdd(&orow[8 * j + 2 * tig + 1], cc[i][j][2 * half + 1]);
                }
            }
        }
    }
#undef ISSUE2
}

// ---------------------------------------------------------------------------
extern "C" void kernel_launch(void* const* d_in, const int* in_sizes, int n_in,
                              void* d_out, int out_size) {
    const float* x   = (const float*)d_in[0];  // [T, H]
    const float* gw  = (const float*)d_in[1];  // [E, H]
    const float* w13 = (const float*)d_in[2];  // [E, 2I, H]
    const float* w2  = (const float*)d_in[3];  // [E, H, I]
    float* out = (float*)d_out;                // [T, H] fp32

    const int dsm = NSTAGE * STG_W * 4;  // 81920 B
    cudaFuncSetAttribute(gemm1_tf32, cudaFuncAttributeMaxDynamicSharedMemorySize, dsm);
    cudaFuncSetAttribute(gemm2_tf32, cudaFuncAttributeMaxDynamicSharedMemorySize, dsm);

    cudaMemsetAsync(out, 0, (size_t)TT * HH * sizeof(float));
    zero_counts_k<<<1, 32>>>();
    router_k<<<TT, 256>>>(x, gw);
    gemm1_tf32<<<dim3(II / 64, TT / 128, EE), 256, dsm>>>(x, w13);
    gemm2_tf32<<<dim3(HH / 128, TT / 128, EE), 256, dsm>>>(w2, out);
}

// round 7
// speedup vs baseline: 3.4521x; 1.1094x over previous
#include <cuda_runtime.h>
#include <math.h>
#include <stdint.h>

#define TT 2048
#define HH 2048
#define EE 8
#define II 4096
#define SROW 36            // smem row stride (words): bank = 4r+t -> conflict-free
#define STG_W 9216         // words/stage: A 128*36 + B 128*36
#define NSTAGE 3
#define BROWS_OFF 4608     // B region word offset (128*36)

// ---- scratch (device globals; no allocations allowed) ----
__device__ int   g_count[EE];
__device__ int   g_tok[EE * TT];
__device__ float g_wt[EE * TT];
__device__ float g_xtf[TT * HH];     // tf32-rounded copy of x (16 MB)
__device__ float g_h[67108864];      // [EE][TT][II] tf32-rounded h (256 MB)

// ---------------------------------------------------------------------------
__global__ void zero_counts_k() {
    if (threadIdx.x < EE) g_count[threadIdx.x] = 0;
}

__device__ __forceinline__ uint32_t f2tf(float f) {
    uint32_t r;
    asm("cvt.rna.tf32.f32 %0, %1;" : "=r"(r) : "f"(f));
    return r;
}
__device__ __forceinline__ void mma8(float* c, const uint32_t* a,
                                     uint32_t b0, uint32_t b1) {
    asm volatile(
        "mma.sync.aligned.m16n8k8.row.col.f32.tf32.tf32.f32 "
        "{%0,%1,%2,%3},{%4,%5,%6,%7},{%8,%9},{%0,%1,%2,%3};"
        : "+f"(c[0]), "+f"(c[1]), "+f"(c[2]), "+f"(c[3])
        : "r"(a[0]), "r"(a[1]), "r"(a[2]), "r"(a[3]), "r"(b0), "r"(b1));
}
#define CP16(so, gp) \
    asm volatile("cp.async.cg.shared.global [%0], [%1], 16;" :: "r"(so), "l"(gp))
#define CP_COMMIT() asm volatile("cp.async.commit_group;" ::: "memory")
#define CP_WAIT1()  asm volatile("cp.async.wait_group 1;" ::: "memory")
#define CP_WAIT0()  asm volatile("cp.async.wait_group 0;" ::: "memory")

// ---------------------------------------------------------------------------
// Router: exact fp32 logits/topk; also emits tf32-rounded x row into g_xtf.
__global__ __launch_bounds__(256) void router_k(const float* __restrict__ x,
                                                const float* __restrict__ gw) {
    const int t = blockIdx.x;
    const int tid = threadIdx.x, w = tid >> 5, lane = tid & 31;
    __shared__ float logits[EE];
    const float* xr = x + (size_t)t * HH;
    const float* gr = gw + (size_t)w * HH;
    float s = 0.f;
    for (int k = lane; k < HH; k += 32) s = fmaf(xr[k], gr[k], s);
#pragma unroll
    for (int o = 16; o; o >>= 1) s += __shfl_xor_sync(0xffffffffu, s, o);
    if (lane == 0) logits[w] = s;
    // tf32 pre-rounded copy of this token's row
    float* xo = g_xtf + (size_t)t * HH;
#pragma unroll
    for (int k = tid; k < HH; k += 256) xo[k] = __uint_as_float(f2tf(xr[k]));
    __syncthreads();
    if (tid == 0) {
        float m = logits[0];
#pragma unroll
        for (int i = 1; i < EE; ++i) m = fmaxf(m, logits[i]);
        float p[EE];
#pragma unroll
        for (int i = 0; i < EE; ++i) p[i] = expf(logits[i] - m);
        int a = 0;
#pragma unroll
        for (int i = 1; i < EE; ++i) if (p[i] > p[a]) a = i;
        int b = (a == 0) ? 1 : 0;
#pragma unroll
        for (int i = 0; i < EE; ++i) if (i != a && p[i] > p[b]) b = i;
        const float r = 1.f / (p[a] + p[b]);
        int pa = atomicAdd(&g_count[a], 1);
        g_tok[a * TT + pa] = t; g_wt[a * TT + pa] = p[a] * r;
        int pb = atomicAdd(&g_count[b], 1);
        g_tok[b * TT + pb] = t; g_wt[b * TT + pb] = p[b] * r;
    }
}

// ---------------------------------------------------------------------------
// GEMM1: block 128(M) x 64(N of gate AND up), BK=32, 3-stage cp.async.
// A = g_xtf (pre-tf32, no cvt). B = w13 fp32 (cvt at fragment load).
__global__ __launch_bounds__(256, 2) void gemm1_tf32(const float* __restrict__ w13) {
    extern __shared__ float sm[];
    const int e = blockIdx.z;
    const int cnt = g_count[e];
    const int m0 = blockIdx.y * 128;
    if (m0 >= cnt) return;
    const int n0 = blockIdx.x * 64;

    const int tid = threadIdx.x;
    const uint32_t sbase = (uint32_t)__cvta_generic_to_shared(sm);

    // loader: 8 CP16/stage (4 A chunks + 4 B chunks)
    const float* aG[4]; uint32_t aS[4];
    const float* bG[4]; uint32_t bS[4];
#pragma unroll
    for (int i = 0; i < 4; ++i) {
        int c = tid + i * 256;
        int r = c >> 3, cg = c & 7;
        int slot = m0 + r; if (slot > cnt - 1) slot = cnt - 1;
        aG[i] = g_xtf + (size_t)g_tok[e * TT + slot] * HH + cg * 4;
        aS[i] = (r * SROW + cg * 4) * 4;
        size_t row = (r < 64) ? (size_t)(n0 + r) : (size_t)(II + n0 + (r - 64));
        bG[i] = w13 + (size_t)e * 2 * II * HH + row * HH + cg * 4;
        bS[i] = (BROWS_OFF + r * SROW + cg * 4) * 4;
    }

#define ISSUE1(s, k0)                                                   \
    {                                                                   \
        const uint32_t sb = sbase + (s) * (STG_W * 4);                  \
        _Pragma("unroll") for (int i = 0; i < 4; ++i) {                 \
            CP16(sb + aS[i], aG[i] + (k0));                             \
            CP16(sb + bS[i], bG[i] + (k0));                             \
        }                                                               \
    }

    const int lane = tid & 31, wid = tid >> 5;
    const int grp = lane >> 2, tig = lane & 3;
    const int wm = (wid & 3) * 32, wn = (wid >> 2) * 32;

    float cgr[2][4][4] = {};
    float cur[2][4][4] = {};

    ISSUE1(0, 0); CP_COMMIT();
    ISSUE1(1, 32); CP_COMMIT();

    const int NT = HH / 32;  // 64
    for (int k = 0; k < NT; ++k) {
        CP_WAIT1();
        __syncthreads();
        const float* st = sm + (k % 3) * STG_W;
        const uint32_t* stu = (const uint32_t*)st;
#pragma unroll
        for (int kc = 0; kc < 32; kc += 8) {
            uint32_t af[2][4];
#pragma unroll
            for (int i = 0; i < 2; ++i) {
                const uint32_t* pa = stu + (wm + 16 * i + grp) * SROW + kc + tig;
                af[i][0] = pa[0];
                af[i][1] = pa[8 * SROW];
                af[i][2] = pa[4];
                af[i][3] = pa[8 * SROW + 4];
            }
#pragma unroll
            for (int j = 0; j < 4; ++j) {
                const float* pg = st + BROWS_OFF + (wn + 8 * j + grp) * SROW + kc + tig;
                const uint32_t bg0 = f2tf(pg[0]);
                const uint32_t bg1 = f2tf(pg[4]);
                const uint32_t bu0 = f2tf(pg[64 * SROW]);
                const uint32_t bu1 = f2tf(pg[64 * SROW + 4]);
#pragma unroll
                for (int i = 0; i < 2; ++i) {
                    mma8(cgr[i][j], af[i], bg0, bg1);
                    mma8(cur[i][j], af[i], bu0, bu1);
                }
            }
        }
        const int kn = k + 2;
        if (kn < NT) ISSUE1(kn % 3, kn * 32);
        CP_COMMIT();
    }
    CP_WAIT0();

    // epilogue: swiglu * wt, tf32-rounded -> g_h
#pragma unroll
    for (int i = 0; i < 2; ++i) {
#pragma unroll
        for (int half = 0; half < 2; ++half) {
            const int slot = m0 + wm + 16 * i + grp + 8 * half;
            if (slot < cnt) {
                const float wt = g_wt[e * TT + slot];
                float* hrow = g_h + ((size_t)e * TT + slot) * II + n0 + wn;
#pragma unroll
                for (int j = 0; j < 4; ++j) {
                    const float g0 = cgr[i][j][2 * half], g1 = cgr[i][j][2 * half + 1];
                    const float u0 = cur[i][j][2 * half], u1 = cur[i][j][2 * half + 1];
                    float2 v;
                    v.x = __uint_as_float(f2tf(wt * (g0 / (1.f + __expf(-g0))) * u0));
                    v.y = __uint_as_float(f2tf(wt * (g1 / (1.f + __expf(-g1))) * u1));
                    *(float2*)&hrow[8 * j + 2 * tig] = v;
                }
            }
        }
    }
#undef ISSUE1
}

// ---------------------------------------------------------------------------
// GEMM2: block 128(M) x 128(N), BK=32, 3-stage. A = g_h (pre-tf32, no cvt).
__global__ __launch_bounds__(256, 2) void gemm2_tf32(const float* __restrict__ w2,
                                                     float* __restrict__ out) {
    extern __shared__ float sm[];
    const int e = blockIdx.z;
    const int cnt = g_count[e];
    const int m0 = blockIdx.y * 128;
    if (m0 >= cnt) return;
    const int n0 = blockIdx.x * 128;

    const int tid = threadIdx.x;
    const uint32_t sbase = (uint32_t)__cvta_generic_to_shared(sm);

    const float* aG[4]; uint32_t aS[4];
    const float* bG[4]; uint32_t bS[4];
#pragma unroll
    for (int i = 0; i < 4; ++i) {
        int c = tid + i * 256;
        int r = c >> 3, cg = c & 7;
        int slot = m0 + r; if (slot > cnt - 1) slot = cnt - 1;
        aG[i] = g_h + ((size_t)e * TT + slot) * II + cg * 4;
        aS[i] = (r * SROW + cg * 4) * 4;
        bG[i] = w2 + (size_t)e * HH * II + (size_t)(n0 + r) * II + cg * 4;
        bS[i] = (BROWS_OFF + r * SROW + cg * 4) * 4;
    }

#define ISSUE2(s, k0)                                                   \
    {                                                                   \
        const uint32_t sb = sbase + (s) * (STG_W * 4);                  \
        _Pragma("unroll") for (int i = 0; i < 4; ++i) {                 \
            CP16(sb + aS[i], aG[i] + (k0));                             \
            CP16(sb + bS[i], bG[i] + (k0));                             \
        }                                                               \
    }

    const int lane = tid & 31, wid = tid >> 5;
    const int grp = lane >> 2, tig = lane & 3;
    const int wm = (wid & 3) * 32, wn = (wid >> 2) * 64;

    float cc[2][8][4] = {};

    ISSUE2(0, 0); CP_COMMIT();
    ISSUE2(1, 32); CP_COMMIT();

    const int NT = II / 32;  // 128
    for (int k = 0; k < NT; ++k) {
        CP_WAIT1();
        __syncthreads();
        const float* st = sm + (k % 3) * STG_W;
        const uint32_t* stu = (const uint32_t*)st;
#pragma unroll
        for (int kc = 0; kc < 32; kc += 8) {
            uint32_t af[2][4];
#pragma unroll
            for (int i = 0; i < 2; ++i) {
                const uint32_t* pa = stu + (wm + 16 * i + grp) * SROW + kc + tig;
                af[i][0] = pa[0];
                af[i][1] = pa[8 * SROW];
                af[i][2] = pa[4];
                af[i][3] = pa[8 * SROW + 4];
            }
#pragma unroll
            for (int j = 0; j < 8; ++j) {
                const float* pb = st + BROWS_OFF + (wn + 8 * j + grp) * SROW + kc + tig;
                const uint32_t b0 = f2tf(pb[0]);
                const uint32_t b1 = f2tf(pb[4]);
#pragma unroll
                for (int i = 0; i < 2; ++i) mma8(cc[i][j], af[i], b0, b1);
            }
        }
        const int kn = k + 2;
        if (kn < NT) ISSUE2(kn % 3, kn * 32);
        CP_COMMIT();
    }
    CP_WAIT0();

#pragma unroll
    for (int i = 0; i < 2; ++i) {
#pragma unroll
        for (int half = 0; half < 2; ++half) {
            const int slot = m0 + wm + 16 * i + grp + 8 * half;
            if (slot < cnt) {
                const int tok = g_tok[e * TT + slot];
                float* orow = out + (size_t)tok * HH + n0 + wn;
#pragma unroll
                for (int j = 0; j < 8; ++j) {
                    atomicAdd(&orow[8 * j + 2 * tig], cc[i][j][2 * half]);
                    atomicAdd(&orow[8 * j + 2 * tig + 1], cc[i][j][2 * half + 1]);
                }
            }
        }
    }
#undef ISSUE2
}

// ---------------------------------------------------------------------------
extern "C" void kernel_launch(void* const* d_in, const int* in_sizes, int n_in,
                              void* d_out, int out_size) {
    const float* x   = (const float*)d_in[0];  // [T, H]
    const float* gw  = (const float*)d_in[1];  // [E, H]
    const float* w13 = (const float*)d_in[2];  // [E, 2I, H]
    const float* w2  = (const float*)d_in[3];  // [E, H, I]
    float* out = (float*)d_out;                // [T, H] fp32

    const int dsm = NSTAGE * STG_W * 4;  // 110592 B
    cudaFuncSetAttribute(gemm1_tf32, cudaFuncAttributeMaxDynamicSharedMemorySize, dsm);
    cudaFuncSetAttribute(gemm2_tf32, cudaFuncAttributeMaxDynamicSharedMemorySize, dsm);

    cudaMemsetAsync(out, 0, (size_t)TT * HH * sizeof(float));
    zero_counts_k<<<1, 32>>>();
    router_k<<<TT, 256>>>(x, gw);
    gemm1_tf32<<<dim3(II / 64, TT / 128, EE), 256, dsm>>>(w13);
    gemm2_tf32<<<dim3(HH / 128, TT / 128, EE), 256, dsm>>>(w2, out);
}

// round 8
// speedup vs baseline: 6.9824x; 2.0227x over previous
#include <cuda_runtime.h>
#include <cuda_fp16.h>
#include <math.h>
#include <stdint.h>

#define TT 2048
#define HH 2048
#define EE 8
#define II 4096
#define NSTAGE 3
#define STGB 32768          // bytes/stage: A 16 KB + B 16 KB (128 rows x 128 B each)
#define BOFF 16384          // B region byte offset within stage

// ---- scratch (device globals; no allocations allowed) ----
__device__ int    g_count[EE];
__device__ int    g_tok[EE * TT];
__device__ float  g_wt[EE * TT];
__device__ __half g_xh[TT * HH];             // fp16 x (8 MB)
__device__ __half g_hh[(size_t)EE * TT * II];// fp16 h (134 MB)
__device__ __half g_w13h[(size_t)EE * 2 * II * HH]; // fp16 w13 (268 MB)
__device__ __half g_w2h[(size_t)EE * HH * II];      // fp16 w2 (134 MB)

// ---------------------------------------------------------------------------
__global__ void zero_counts_k() {
    if (threadIdx.x < EE) g_count[threadIdx.x] = 0;
}

// One-time (per launch) weight conversion fp32 -> fp16.
__global__ __launch_bounds__(256) void cvt_w_k(const float* __restrict__ w13,
                                               const float* __restrict__ w2) {
    const size_t n13 = (size_t)EE * 2 * II * HH / 4;  // float4 count
    const size_t n2  = (size_t)EE * HH * II / 4;
    const size_t stride = (size_t)gridDim.x * blockDim.x;
    for (size_t i = (size_t)blockIdx.x * blockDim.x + threadIdx.x;
         i < n13 + n2; i += stride) {
        if (i < n13) {
            float4 v = ((const float4*)w13)[i];
            __half2 h0 = __floats2half2_rn(v.x, v.y);
            __half2 h1 = __floats2half2_rn(v.z, v.w);
            ((__half2*)g_w13h)[2 * i] = h0;
            ((__half2*)g_w13h)[2 * i + 1] = h1;
        } else {
            size_t j = i - n13;
            float4 v = ((const float4*)w2)[j];
            __half2 h0 = __floats2half2_rn(v.x, v.y);
            __half2 h1 = __floats2half2_rn(v.z, v.w);
            ((__half2*)g_w2h)[2 * j] = h0;
            ((__half2*)g_w2h)[2 * j + 1] = h1;
        }
    }
}

// Router: exact fp32 logits/topk; also writes fp16 x row.
__global__ __launch_bounds__(256) void router_k(const float* __restrict__ x,
                                                const float* __restrict__ gw) {
    const int t = blockIdx.x;
    const int tid = threadIdx.x, w = tid >> 5, lane = tid & 31;
    __shared__ float logits[EE];
    const float* xr = x + (size_t)t * HH;
    const float* gr = gw + (size_t)w * HH;
    float s = 0.f;
    for (int k = lane; k < HH; k += 32) s = fmaf(xr[k], gr[k], s);
#pragma unroll
    for (int o = 16; o; o >>= 1) s += __shfl_xor_sync(0xffffffffu, s, o);
    if (lane == 0) logits[w] = s;
    __half* xo = g_xh + (size_t)t * HH;
    for (int k = tid; k < HH; k += 256) xo[k] = __float2half_rn(xr[k]);
    __syncthreads();
    if (tid == 0) {
        float m = logits[0];
#pragma unroll
        for (int i = 1; i < EE; ++i) m = fmaxf(m, logits[i]);
        float p[EE];
#pragma unroll
        for (int i = 0; i < EE; ++i) p[i] = expf(logits[i] - m);
        int a = 0;
#pragma unroll
        for (int i = 1; i < EE; ++i) if (p[i] > p[a]) a = i;
        int b = (a == 0) ? 1 : 0;
#pragma unroll
        for (int i = 0; i < EE; ++i) if (i != a && p[i] > p[b]) b = i;
        const float r = 1.f / (p[a] + p[b]);
        int pa = atomicAdd(&g_count[a], 1);
        g_tok[a * TT + pa] = t; g_wt[a * TT + pa] = p[a] * r;
        int pb = atomicAdd(&g_count[b], 1);
        g_tok[b * TT + pb] = t; g_wt[b * TT + pb] = p[b] * r;
    }
}

// ---------------------------------------------------------------------------
__device__ __forceinline__ uint32_t swz(uint32_t o) { return o ^ ((o >> 3) & 0x70); }

__device__ __forceinline__ void mma16(float* c, const uint32_t* a,
                                      uint32_t b0, uint32_t b1) {
    asm volatile(
        "mma.sync.aligned.m16n8k16.row.col.f32.f16.f16.f32 "
        "{%0,%1,%2,%3},{%4,%5,%6,%7},{%8,%9},{%0,%1,%2,%3};"
        : "+f"(c[0]), "+f"(c[1]), "+f"(c[2]), "+f"(c[3])
        : "r"(a[0]), "r"(a[1]), "r"(a[2]), "r"(a[3]), "r"(b0), "r"(b1));
}
#define LDM4(r, addr)                                                        \
    asm volatile("ldmatrix.sync.aligned.m8n8.x4.shared.b16 {%0,%1,%2,%3},[%4];" \
                 : "=r"((r)[0]), "=r"((r)[1]), "=r"((r)[2]), "=r"((r)[3])    \
                 : "r"(addr))
#define CP16(so, gp) \
    asm volatile("cp.async.cg.shared.global [%0], [%1], 16;" :: "r"(so), "l"(gp))
#define CP_COMMIT() asm volatile("cp.async.commit_group;" ::: "memory")
#define CP_WAIT1()  asm volatile("cp.async.wait_group 1;" ::: "memory")
#define CP_WAIT0()  asm volatile("cp.async.wait_group 0;" ::: "memory")

// ---------------------------------------------------------------------------
// GEMM1: block 128(M) x 64(N of gate AND up), BK=64 halves, 3-stage cp.async,
// all-fp16 smem with SW128 swizzle + ldmatrix. Warps 4(M) x 2(N);
// warp tile 32x32 dual accumulator (gate+up).
__global__ __launch_bounds__(256, 2) void gemm1_fp16() {
    extern __shared__ char smraw[];
    char* smal = (char*)(((uintptr_t)smraw + 1023) & ~(uintptr_t)1023);
    const int e = blockIdx.z;
    const int cnt = g_count[e];
    const int m0 = blockIdx.y * 128;
    if (m0 >= cnt) return;
    const int n0 = blockIdx.x * 64;

    const int tid = threadIdx.x;
    const uint32_t sbase = (uint32_t)__cvta_generic_to_shared(smal);

    // staging: per thread 4 A chunks + 4 B chunks (16 B each)
    const __half* aG[4]; uint32_t aS[4];
    const __half* bG[4]; uint32_t bS[4];
#pragma unroll
    for (int i = 0; i < 4; ++i) {
        int c = tid + i * 256;
        int r = c >> 3, kg = c & 7;
        int slot = m0 + r; if (slot > cnt - 1) slot = cnt - 1;
        aG[i] = g_xh + (size_t)g_tok[e * TT + slot] * HH + kg * 8;
        aS[i] = swz(r * 128 + kg * 16);
        size_t row = (r < 64) ? (size_t)(n0 + r) : (size_t)(II + n0 + (r - 64));
        bG[i] = g_w13h + (size_t)e * 2 * II * HH + row * HH + kg * 8;
        bS[i] = BOFF + swz(r * 128 + kg * 16);
    }

#define ISSUE1(s, k0)                                                   \
    {                                                                   \
        const uint32_t sb = sbase + (s) * STGB;                         \
        _Pragma("unroll") for (int i = 0; i < 4; ++i) {                 \
            CP16(sb + aS[i], aG[i] + (k0));                             \
            CP16(sb + bS[i], bG[i] + (k0));                             \
        }                                                               \
    }

    const int lane = tid & 31, wid = tid >> 5;
    const int grp = lane >> 2, tig = lane & 3;
    const int wm = (wid & 3) * 32, wn = (wid >> 2) * 32;

    // ldmatrix address precompute (add-then-xor form)
    const uint32_t arel = (uint32_t)(wm + (lane & 15)) * 128 + ((lane >> 4) & 1) * 16;
    const uint32_t amask = (arel >> 3) & 0x70;
    const uint32_t brel = (uint32_t)(wn + ((lane >> 4) & 1) * 8 + (lane & 7)) * 128
                        + ((lane >> 3) & 1) * 16;
    const uint32_t bmask = (brel >> 3) & 0x70;

    float cgr[2][4][4] = {};
    float cur[2][4][4] = {};

    ISSUE1(0, 0); CP_COMMIT();
    ISSUE1(1, 64); CP_COMMIT();

    const int NT = HH / 64;  // 32
    for (int k = 0; k < NT; ++k) {
        CP_WAIT1();
        __syncthreads();
        const uint32_t su = sbase + (k % 3) * STGB;
#pragma unroll
        for (int kc4 = 0; kc4 < 4; ++kc4) {
            const uint32_t kcb = kc4 * 32;
            uint32_t af[2][4];
#pragma unroll
            for (int i = 0; i < 2; ++i)
                LDM4(af[i], su + (((arel + kcb + 2048 * i) ^ amask)));
#pragma unroll
            for (int jj = 0; jj < 2; ++jj) {
                uint32_t bg[4], bu[4];
                const uint32_t bb = brel + kcb + 2048 * jj;
                LDM4(bg, su + BOFF + ((bb) ^ bmask));
                LDM4(bu, su + BOFF + ((bb + 8192) ^ bmask));
#pragma unroll
                for (int i = 0; i < 2; ++i) {
                    mma16(cgr[i][2 * jj],     af[i], bg[0], bg[1]);
                    mma16(cgr[i][2 * jj + 1], af[i], bg[2], bg[3]);
                    mma16(cur[i][2 * jj],     af[i], bu[0], bu[1]);
                    mma16(cur[i][2 * jj + 1], af[i], bu[2], bu[3]);
                }
            }
        }
        const int kn = k + 2;
        if (kn < NT) ISSUE1(kn % 3, kn * 64);
        CP_COMMIT();
    }
    CP_WAIT0();

    // epilogue: swiglu * wt -> g_hh (fp16)
#pragma unroll
    for (int i = 0; i < 2; ++i) {
#pragma unroll
        for (int half = 0; half < 2; ++half) {
            const int slot = m0 + wm + 16 * i + grp + 8 * half;
            if (slot < cnt) {
                const float wt = g_wt[e * TT + slot];
                __half* hrow = g_hh + ((size_t)e * TT + slot) * II + n0 + wn;
#pragma unroll
                for (int j = 0; j < 4; ++j) {
                    const float g0 = cgr[i][j][2 * half], g1 = cgr[i][j][2 * half + 1];
                    const float u0 = cur[i][j][2 * half], u1 = cur[i][j][2 * half + 1];
                    const float v0 = wt * (g0 / (1.f + __expf(-g0))) * u0;
                    const float v1 = wt * (g1 / (1.f + __expf(-g1))) * u1;
                    *(__half2*)&hrow[8 * j + 2 * tig] = __floats2half2_rn(v0, v1);
                }
            }
        }
    }
#undef ISSUE1
}

// ---------------------------------------------------------------------------
// GEMM2: block 128(M) x 128(N), BK=64 halves, 3-stage, all-fp16 + ldmatrix.
// Warps 4(M) x 2(N); warp tile 32x64. Scatter atomicAdd epilogue.
__global__ __launch_bounds__(256, 2) void gemm2_fp16(float* __restrict__ out) {
    extern __shared__ char smraw[];
    char* smal = (char*)(((uintptr_t)smraw + 1023) & ~(uintptr_t)1023);
    const int e = blockIdx.z;
    const int cnt = g_count[e];
    const int m0 = blockIdx.y * 128;
    if (m0 >= cnt) return;
    const int n0 = blockIdx.x * 128;

    const int tid = threadIdx.x;
    const uint32_t sbase = (uint32_t)__cvta_generic_to_shared(smal);

    const __half* aG[4]; uint32_t aS[4];
    const __half* bG[4]; uint32_t bS[4];
#pragma unroll
    for (int i = 0; i < 4; ++i) {
        int c = tid + i * 256;
        int r = c >> 3, kg = c & 7;
        int slot = m0 + r; if (slot > cnt - 1) slot = cnt - 1;
        aG[i] = g_hh + ((size_t)e * TT + slot) * II + kg * 8;
        aS[i] = swz(r * 128 + kg * 16);
        bG[i] = g_w2h + (size_t)e * HH * II + (size_t)(n0 + r) * II + kg * 8;
        bS[i] = BOFF + swz(r * 128 + kg * 16);
    }

#define ISSUE2(s, k0)                                                   \
    {                                                                   \
        const uint32_t sb = sbase + (s) * STGB;                         \
        _Pragma("unroll") for (int i = 0; i < 4; ++i) {                 \
            CP16(sb + aS[i], aG[i] + (k0));                             \
            CP16(sb + bS[i], bG[i] + (k0));                             \
        }                                                               \
    }

    const int lane = tid & 31, wid = tid >> 5;
    const int grp = lane >> 2, tig = lane & 3;
    const int wm = (wid & 3) * 32, wn = (wid >> 2) * 64;

    const uint32_t arel = (uint32_t)(wm + (lane & 15)) * 128 + ((lane >> 4) & 1) * 16;
    const uint32_t amask = (arel >> 3) & 0x70;
    const uint32_t brel = (uint32_t)(wn + ((lane >> 4) & 1) * 8 + (lane & 7)) * 128
                        + ((lane >> 3) & 1) * 16;
    const uint32_t bmask = (brel >> 3) & 0x70;

    float cc[2][8][4] = {};

    ISSUE2(0, 0); CP_COMMIT();
    ISSUE2(1, 64); CP_COMMIT();

    const int NT = II / 64;  // 64
    for (int k = 0; k < NT; ++k) {
        CP_WAIT1();
        __syncthreads();
        const uint32_t su = sbase + (k % 3) * STGB;
#pragma unroll
        for (int kc4 = 0; kc4 < 4; ++kc4) {
            const uint32_t kcb = kc4 * 32;
            uint32_t af[2][4];
#pragma unroll
            for (int i = 0; i < 2; ++i)
                LDM4(af[i], su + (((arel + kcb + 2048 * i) ^ amask)));
#pragma unroll
            for (int jj = 0; jj < 4; ++jj) {
                uint32_t bb4[4];
                LDM4(bb4, su + BOFF + (((brel + kcb + 2048 * jj) ^ bmask)));
#pragma unroll
                for (int i = 0; i < 2; ++i) {
                    mma16(cc[i][2 * jj],     af[i], bb4[0], bb4[1]);
                    mma16(cc[i][2 * jj + 1], af[i], bb4[2], bb4[3]);
                }
            }
        }
        const int kn = k + 2;
        if (kn < NT) ISSUE2(kn % 3, kn * 64);
        CP_COMMIT();
    }
    CP_WAIT0();

#pragma unroll
    for (int i = 0; i < 2; ++i) {
#pragma unroll
        for (int half = 0; half < 2; ++half) {
            const int slot = m0 + wm + 16 * i + grp + 8 * half;
            if (slot < cnt) {
                const int tok = g_tok[e * TT + slot];
                float* orow = out + (size_t)tok * HH + n0 + wn;
#pragma unroll
                for (int j = 0; j < 8; ++j) {
                    atomicAdd(&orow[8 * j + 2 * tig], cc[i][j][2 * half]);
                    atomicAdd(&orow[8 * j + 2 * tig + 1], cc[i][j][2 * half + 1]);
                }
            }
        }
    }
#undef ISSUE2
}

// ---------------------------------------------------------------------------
extern "C" void kernel_launch(void* const* d_in, const int* in_sizes, int n_in,
                              void* d_out, int out_size) {
    const float* x   = (const float*)d_in[0];  // [T, H]
    const float* gw  = (const float*)d_in[1];  // [E, H]
    const float* w13 = (const float*)d_in[2];  // [E, 2I, H]
    const float* w2  = (const float*)d_in[3];  // [E, H, I]
    float* out = (float*)d_out;                // [T, H] fp32

    const int dsm = NSTAGE * STGB + 1024;  // 99328 B
    cudaFuncSetAttribute(gemm1_fp16, cudaFuncAttributeMaxDynamicSharedMemorySize, dsm);
    cudaFuncSetAttribute(gemm2_fp16, cudaFuncAttributeMaxDynamicSharedMemorySize, dsm);

    cudaMemsetAsync(out, 0, (size_t)TT * HH * sizeof(float));
    zero_counts_k<<<1, 32>>>();
    cvt_w_k<<<4096, 256>>>(w13, w2);
    router_k<<<TT, 256>>>(x, gw);
    gemm1_fp16<<<dim3(II / 64, TT / 128, EE), 256, dsm>>>();
    gemm2_fp16<<<dim3(HH / 128, TT / 128, EE), 256, dsm>>>(out);
}